// round 13
// baseline (speedup 1.0000x reference)
#include <cuda_runtime.h>
#include <cuda_fp16.h>
#include <cstdint>

#define NB 8192
#define FD 4096
#define NH 16
#define HI 256
#define HO 1024
#define MD 16384

// Scratch (device globals — no allocation in kernel_launch)
__device__ __half g_xperm[NB * FD];                 // 64 MB
__device__ __half g_w1[NH * HI * HO];               // 8 MB  [h][k=HI][n=HO]
__device__ __half g_w2[NH * HO * HI];               // 8 MB  [h][k=HO][n=HI]

__device__ __forceinline__ float gelu_f(float v) {
    return 0.5f * v * (1.0f + erff(v * 0.7071067811865476f));
}
__device__ __forceinline__ void ldsm4(unsigned &r0, unsigned &r1, unsigned &r2, unsigned &r3, unsigned addr) {
    asm volatile("ldmatrix.sync.aligned.m8n8.x4.shared.b16 {%0,%1,%2,%3},[%4];"
                 : "=r"(r0), "=r"(r1), "=r"(r2), "=r"(r3) : "r"(addr));
}
__device__ __forceinline__ void ldsm4t(unsigned &r0, unsigned &r1, unsigned &r2, unsigned &r3, unsigned addr) {
    asm volatile("ldmatrix.sync.aligned.m8n8.x4.trans.shared.b16 {%0,%1,%2,%3},[%4];"
                 : "=r"(r0), "=r"(r1), "=r"(r2), "=r"(r3) : "r"(addr));
}
__device__ __forceinline__ void mma16816(float c[4], const unsigned a[4], const unsigned b[2]) {
    asm volatile("mma.sync.aligned.m16n8k16.row.col.f32.f16.f16.f32 "
                 "{%0,%1,%2,%3},{%4,%5,%6,%7},{%8,%9},{%0,%1,%2,%3};"
                 : "+f"(c[0]), "+f"(c[1]), "+f"(c[2]), "+f"(c[3])
                 : "r"(a[0]), "r"(a[1]), "r"(a[2]), "r"(a[3]), "r"(b[0]), "r"(b[1]));
}
#define CP16(s, g) asm volatile("cp.async.cg.shared.global [%0], [%1], 16;\n" :: "r"(s), "l"(g))

// ---------------------------------------------------------------------------
// Prep kernels (unchanged, validated)
// ---------------------------------------------------------------------------
__global__ void __launch_bounds__(256) k_prep_x(const float* __restrict__ x,
                                                const int* __restrict__ perm) {
    int i = blockIdx.x * 256 + threadIdx.x;
    if (i >= NB * FD / 4) return;
    int b  = i >> 10;
    int k4 = (i & 1023) << 2;
    int p  = __ldg(perm + k4);
    const float4 v = *(const float4*)(x + (long long)b * FD + p);
    __half2* dst = (__half2*)(g_xperm + (long long)b * FD + k4);
    dst[0] = __floats2half2_rn(v.x, v.y);
    dst[1] = __floats2half2_rn(v.z, v.w);
}

__global__ void __launch_bounds__(256) k_prep_w(const float* __restrict__ wu,
                                                const float* __restrict__ wd) {
    int i = blockIdx.x * 256 + threadIdx.x;
    const int N4 = NH * HI * HO / 4;
    if (i >= N4) return;
    float4 a = *(const float4*)(wu + (long long)i * 4);
    __half2* d1 = (__half2*)(g_w1 + (long long)i * 4);
    d1[0] = __floats2half2_rn(a.x, a.y);
    d1[1] = __floats2half2_rn(a.z, a.w);
    float4 b = *(const float4*)(wd + (long long)i * 4);
    __half2* d2 = (__half2*)(g_w2 + (long long)i * 4);
    d2[0] = __floats2half2_rn(b.x, b.y);
    d2[1] = __floats2half2_rn(b.z, b.w);
}

// ---------------------------------------------------------------------------
// Fused MLP kernel. CTA = (head h, 64-row block). 8 warps (2 M x 4 N).
// smem layout (dynamic, 229376 B):
//   [0, 128K)          H: 16 k-chunks x (64 rows x 128 B)  [swizzled A-layout]
//   [128K, 160K)       X: 4 k-chunks x (64 x 128 B)        [phase 1 only]
//   [160K, 208K)       W1 stages: 3 x 16 KB                [phase 1 only]
//   [128K, 224K)       W2 stages: 3 x 32 KB                [phase 2, reuses X/W1]
// Phase 1: for 8 n-chunks x 4 k-tiles: H_chunk = gelu(X @ W1 + b_up) -> smem H
// Phase 2: out[:, perm[c]] = H @ W2 + b_down (K=1024, 16 k-tiles)
// ---------------------------------------------------------------------------
__global__ void __launch_bounds__(256, 1) k_fused(const float* __restrict__ b_up,
                                                  const float* __restrict__ b_down,
                                                  const int* __restrict__ perm,
                                                  float* __restrict__ out) {
    extern __shared__ char smem[];
    const unsigned sH = (unsigned)__cvta_generic_to_shared(smem);
    const unsigned sX = sH + 131072u;
    const unsigned sW1 = sH + 163840u;     // 3 x 16384
    const unsigned sW2 = sH + 131072u;     // 3 x 32768

    const int h = blockIdx.x;
    const long long R0 = (long long)blockIdx.y << 6;   // 64 rows per CTA
    const int tid = threadIdx.x;
    const int lane = tid & 31, warp = tid >> 5;
    const int wm = warp & 1, wn = warp >> 1;           // 2 M x 4 N
    const int g = lane >> 2, t = lane & 3;

    const __half* Xg  = g_xperm + R0 * FD + h * HI;
    const __half* W1g = g_w1 + (long long)h * HI * HO;
    const __half* W2g = g_w2 + (long long)h * HO * HI;

    // ---- X load (once): 64 x 256 halfs = 2048 granules, 8 per thread ----
#pragma unroll
    for (int i = 0; i < 8; i++) {
        int c = tid + i * 256;
        int m = c >> 5, gk = c & 31;               // row, granule-in-row
        CP16(sX + (gk >> 3) * 8192 + m * 128 + (((gk & 7) ^ (m & 7)) << 4),
             Xg + (long long)m * FD + gk * 8);
    }
    asm volatile("cp.async.commit_group;\n");

    auto loadW1 = [&](int st, int s) {
        const __half* Bk = W1g + (long long)((s & 3) * 64) * HO + (s >> 2) * 128;
        const unsigned sb = sW1 + (unsigned)st * 16384u;
#pragma unroll
        for (int i = 0; i < 4; i++) {
            int c = tid + i * 256;
            int k = c >> 4, cn = c & 15;
            CP16(sb + k * 256 + ((cn ^ ((k & 7) << 1)) << 4),
                 Bk + (long long)k * HO + cn * 8);
        }
        asm volatile("cp.async.commit_group;\n");
    };

    loadW1(0, 0);
    loadW1(1, 1);

    // ---- Phase 1: 32 tiles (8 n-chunks x 4 k-tiles), k_up_res loop shape ----
    {
        float acc[2][4][4] = {};
        for (int s = 0; s < 32; s++) {
            if (s + 1 < 32) asm volatile("cp.async.wait_group 1;\n");
            else            asm volatile("cp.async.wait_group 0;\n");
            __syncthreads();
            if (s + 2 < 32) loadW1((s + 2) % 3, s + 2);

            const unsigned sb = sW1 + (unsigned)(s % 3) * 16384u;
            const unsigned sa = sX + (unsigned)(s & 3) * 8192u;
#pragma unroll
            for (int ks = 0; ks < 4; ks++) {
                const int k16 = ks * 2 + (lane >> 4);
                unsigned af[2][4];
#pragma unroll
                for (int mi = 0; mi < 2; mi++) {
                    int m = wm * 32 + mi * 16 + (lane & 15);
                    ldsm4(af[mi][0], af[mi][1], af[mi][2], af[mi][3],
                          sa + m * 128 + ((k16 ^ (m & 7)) << 4));
                }
                unsigned bf[4][2];
#pragma unroll
                for (int nj = 0; nj < 2; nj++) {
                    int kk = ks * 16 + (lane & 15);
                    int cn = wn * 4 + nj * 2 + (lane >> 4);
                    unsigned t0, t1, t2, t3;
                    ldsm4t(t0, t1, t2, t3, sb + kk * 256 + ((cn ^ ((kk & 7) << 1)) << 4));
                    bf[nj * 2][0] = t0; bf[nj * 2][1] = t1;
                    bf[nj * 2 + 1][0] = t2; bf[nj * 2 + 1][1] = t3;
                }
#pragma unroll
                for (int mi = 0; mi < 2; mi++)
#pragma unroll
                    for (int ni = 0; ni < 4; ni++)
                        mma16816(acc[mi][ni], af[mi], bf[ni]);
            }

            if ((s & 3) == 3) {
                // Epilogue for n-chunk s>>2: gelu -> H smem (swizzled A-layout)
                const int nchunk = s >> 2;
#pragma unroll
                for (int mi = 0; mi < 2; mi++) {
#pragma unroll
                    for (int ni = 0; ni < 4; ni++) {
                        int r  = wm * 32 + mi * 16 + g;
                        int C  = nchunk * 128 + wn * 32 + ni * 8 + t * 2;  // 0..1023
                        float b0 = __ldg(b_up + h * HO + C);
                        float b1 = __ldg(b_up + h * HO + C + 1);
                        const int base = (C >> 6) * 8192 + ((((C >> 3) & 7) ^ (r & 7)) << 4) + (C & 7) * 2;
                        float v0 = gelu_f(acc[mi][ni][0] + b0);
                        float v1 = gelu_f(acc[mi][ni][1] + b1);
                        *(__half2*)(smem + base + r * 128) = __floats2half2_rn(v0, v1);
                        v0 = gelu_f(acc[mi][ni][2] + b0);
                        v1 = gelu_f(acc[mi][ni][3] + b1);
                        const int r8 = r + 8;
                        const int base8 = (C >> 6) * 8192 + ((((C >> 3) & 7) ^ (r8 & 7)) << 4) + (C & 7) * 2;
                        *(__half2*)(smem + base8 + r8 * 128) = __floats2half2_rn(v0, v1);
                        acc[mi][ni][0] = acc[mi][ni][1] = acc[mi][ni][2] = acc[mi][ni][3] = 0.f;
                    }
                }
            }
        }
    }
    __syncthreads();   // H complete; X/W1 regions now dead

    // ---- Phase 2: K=1024 over 16 k-tiles, k_down loop shape, A = smem H ----
    auto loadW2 = [&](int st, int kt) {
        const __half* Bk = W2g + (long long)(kt * 64) * HI;
        const unsigned sb = sW2 + (unsigned)st * 32768u;
#pragma unroll
        for (int i = 0; i < 8; i++) {
            int c = tid + i * 256;
            int sub = c >> 10, cc = c & 1023;
            int k = cc >> 4, cn = cc & 15;
            CP16(sb + sub * 16384 + k * 256 + ((cn ^ ((k & 7) << 1)) << 4),
                 Bk + (long long)k * HI + sub * 128 + cn * 8);
        }
        asm volatile("cp.async.commit_group;\n");
    };

    float acc2[2][8][4] = {};
    loadW2(0, 0);

    for (int kt = 0; kt < 16; kt++) {
        if (kt + 1 < 16) {
            loadW2((kt + 1) % 3, kt + 1);
            asm volatile("cp.async.wait_group 1;\n");
        } else {
            asm volatile("cp.async.wait_group 0;\n");
        }
        __syncthreads();
        const unsigned sa = sH + (unsigned)kt * 8192u;
        const unsigned sb = sW2 + (unsigned)(kt % 3) * 32768u + (unsigned)(wn >> 1) * 16384u;
#pragma unroll
        for (int ks = 0; ks < 4; ks++) {
            const int k16 = ks * 2 + (lane >> 4);
            unsigned af[2][4];
#pragma unroll
            for (int mi = 0; mi < 2; mi++) {
                int m = wm * 32 + mi * 16 + (lane & 15);
                ldsm4(af[mi][0], af[mi][1], af[mi][2], af[mi][3],
                      sa + m * 128 + ((k16 ^ (m & 7)) << 4));
            }
            unsigned bf[8][2];
#pragma unroll
            for (int nj = 0; nj < 4; nj++) {
                int kk = ks * 16 + (lane & 15);
                int cn = (wn & 1) * 8 + nj * 2 + (lane >> 4);
                unsigned t0, t1, t2, t3;
                ldsm4t(t0, t1, t2, t3, sb + kk * 256 + ((cn ^ ((kk & 7) << 1)) << 4));
                bf[nj * 2][0] = t0; bf[nj * 2][1] = t1;
                bf[nj * 2 + 1][0] = t2; bf[nj * 2 + 1][1] = t3;
            }
#pragma unroll
            for (int mi = 0; mi < 2; mi++)
#pragma unroll
                for (int ni = 0; ni < 8; ni++)
                    mma16816(acc2[mi][ni], af[mi], bf[ni]);
        }
    }

    // ---- Phase 2 epilogue: +b_down, scatter via perm (validated) ----
#pragma unroll
    for (int mi = 0; mi < 2; mi++) {
#pragma unroll
        for (int ni = 0; ni < 8; ni++) {
            long long r = R0 + wm * 32 + mi * 16 + g;
            int c = h * HI + wn * 64 + ni * 8 + t * 2;
            float b0 = __ldg(b_down + c), b1 = __ldg(b_down + c + 1);
            int p = __ldg(perm + c);   // c even; 64-chunk perm => perm[c+1]=perm[c]+1
            float2 o0; o0.x = acc2[mi][ni][0] + b0; o0.y = acc2[mi][ni][1] + b1;
            *(float2*)(out + r * FD + p) = o0;
            float2 o1; o1.x = acc2[mi][ni][2] + b0; o1.y = acc2[mi][ni][3] + b1;
            *(float2*)(out + (r + 8) * FD + p) = o1;
        }
    }
}

extern "C" void kernel_launch(void* const* d_in, const int* in_sizes, int n_in,
                              void* d_out, int out_size) {
    const float* x      = (const float*)d_in[0];
    const int*   perm   = (const int*)d_in[1];
    const float* w_up   = (const float*)d_in[2];
    const float* b_up   = (const float*)d_in[3];
    const float* w_down = (const float*)d_in[4];
    const float* b_down = (const float*)d_in[5];
    float* out = (float*)d_out;

    k_prep_x<<<(NB * FD / 4 + 255) / 256, 256>>>(x, perm);
    k_prep_w<<<(NH * HI * HO / 4 + 255) / 256, 256>>>(w_up, w_down);

    constexpr int SMEM = 131072 + 98304;   // 229376 B (H + phase-2 stage region)
    cudaFuncSetAttribute(k_fused, cudaFuncAttributeMaxDynamicSharedMemorySize, SMEM);

    dim3 gf(NH, NB / 64);   // (16, 128) = 2048 CTAs
    k_fused<<<gf, 256, SMEM>>>(b_up, b_down, perm, out);
}

// round 14
// speedup vs baseline: 1.2741x; 1.2741x over previous
#include <cuda_runtime.h>
#include <cuda_fp16.h>
#include <cstdint>

#define NB 8192
#define FD 4096
#define NH 16
#define HI 256
#define HO 1024
#define MD 16384

// Scratch (device globals — no allocation in kernel_launch)
__device__ __half g_xperm[NB * FD];                 // 64 MB
__device__ __half g_w1[NH * HI * HO];               // 8 MB  [h][k=HI][n=HO]
__device__ __half g_w2[NH * HO * HI];               // 8 MB  [h][k=HO][n=HI]
__device__ __half g_h[(long long)NB * MD];          // 256 MB

__device__ __forceinline__ float gelu_f(float v) {
    return 0.5f * v * (1.0f + erff(v * 0.7071067811865476f));
}
__device__ __forceinline__ void ldsm4(unsigned &r0, unsigned &r1, unsigned &r2, unsigned &r3, unsigned addr) {
    asm volatile("ldmatrix.sync.aligned.m8n8.x4.shared.b16 {%0,%1,%2,%3},[%4];"
                 : "=r"(r0), "=r"(r1), "=r"(r2), "=r"(r3) : "r"(addr));
}
__device__ __forceinline__ void ldsm4t(unsigned &r0, unsigned &r1, unsigned &r2, unsigned &r3, unsigned addr) {
    asm volatile("ldmatrix.sync.aligned.m8n8.x4.trans.shared.b16 {%0,%1,%2,%3},[%4];"
                 : "=r"(r0), "=r"(r1), "=r"(r2), "=r"(r3) : "r"(addr));
}
__device__ __forceinline__ void mma16816(float c[4], const unsigned a[4], const unsigned b[2]) {
    asm volatile("mma.sync.aligned.m16n8k16.row.col.f32.f16.f16.f32 "
                 "{%0,%1,%2,%3},{%4,%5,%6,%7},{%8,%9},{%0,%1,%2,%3};"
                 : "+f"(c[0]), "+f"(c[1]), "+f"(c[2]), "+f"(c[3])
                 : "r"(a[0]), "r"(a[1]), "r"(a[2]), "r"(a[3]), "r"(b[0]), "r"(b[1]));
}
#define CP16(s, g) asm volatile("cp.async.cg.shared.global [%0], [%1], 16;\n" :: "r"(s), "l"(g))

// ---------------------------------------------------------------------------
// Prep kernels (unchanged, validated)
// ---------------------------------------------------------------------------
__global__ void __launch_bounds__(256) k_prep_x(const float* __restrict__ x,
                                                const int* __restrict__ perm) {
    int i = blockIdx.x * 256 + threadIdx.x;
    if (i >= NB * FD / 4) return;
    int b  = i >> 10;
    int k4 = (i & 1023) << 2;
    int p  = __ldg(perm + k4);
    const float4 v = *(const float4*)(x + (long long)b * FD + p);
    __half2* dst = (__half2*)(g_xperm + (long long)b * FD + k4);
    dst[0] = __floats2half2_rn(v.x, v.y);
    dst[1] = __floats2half2_rn(v.z, v.w);
}

__global__ void __launch_bounds__(256) k_prep_w(const float* __restrict__ wu,
                                                const float* __restrict__ wd) {
    int i = blockIdx.x * 256 + threadIdx.x;
    const int N4 = NH * HI * HO / 4;
    if (i >= N4) return;
    float4 a = *(const float4*)(wu + (long long)i * 4);
    __half2* d1 = (__half2*)(g_w1 + (long long)i * 4);
    d1[0] = __floats2half2_rn(a.x, a.y);
    d1[1] = __floats2half2_rn(a.z, a.w);
    float4 b = *(const float4*)(wd + (long long)i * 4);
    __half2* d2 = (__half2*)(g_w2 + (long long)i * 4);
    d2[0] = __floats2half2_rn(b.x, b.y);
    d2[1] = __floats2half2_rn(b.z, b.w);
}

// ---------------------------------------------------------------------------
// k_up_ares: GEMM1 with A-RESIDENT smem.
// CTA = (head, 128-row block), grid (16, 64). A = X[r0:r0+128, h*256:(h+1)*256]
// (64 KB, 4 k-chunks of 128x128B, swizzled) loaded ONCE. W1 streamed as
// 8 n-chunks x 4 k-tiles = 32 tiles (16 KB), 3-stage cp.async, distance-2
// prefetch issued after the barrier (race-free: stages s, s+1, s+2 distinct
// mod 3). 8 warps 4x2, warp tile 32x64 (the proven operating point).
// Per-n-chunk epilogue: gelu(acc + b_up) -> g_h fp16 (R8 epilogue, verbatim).
// ---------------------------------------------------------------------------
__global__ void __launch_bounds__(256, 2) k_up_ares(const float* __restrict__ bias) {
    extern __shared__ char smem[];
    constexpr int BSTG = 64 * 256;         // 16 KB per W1 stage
    const unsigned sAb = (unsigned)__cvta_generic_to_shared(smem);   // 64 KB A
    const unsigned sBb = sAb + 65536u;                               // 3 x 16 KB B

    const int h  = blockIdx.x;
    const int r0 = blockIdx.y << 7;
    const int tid = threadIdx.x;
    const int lane = tid & 31, warp = tid >> 5;
    const int wm = warp & 3, wn = warp >> 2;

    const __half* Ag = g_xperm + (long long)r0 * FD + h * HI;
    const __half* W1g = g_w1 + (long long)h * HI * HO;

    // ---- A load (once): 128 rows x 32 granules = 4096, 16 per thread ----
#pragma unroll
    for (int i = 0; i < 16; i++) {
        int c = tid + i * 256;
        int m = c >> 5, gk = c & 31;          // row, 16B-granule in row
        CP16(sAb + (gk >> 3) * 16384 + m * 128 + (((gk & 7) ^ (m & 7)) << 4),
             Ag + (long long)m * FD + gk * 8);
    }
    asm volatile("cp.async.commit_group;\n");

    // W1 tile for step s: k-tile (s&3)*64, n-chunk (s>>2)*128
    auto loadB = [&](int st, int s) {
        const __half* Bk = W1g + (long long)((s & 3) * 64) * HO + (s >> 2) * 128;
        const unsigned sb = sBb + (unsigned)st * BSTG;
#pragma unroll
        for (int i = 0; i < 4; i++) {
            int c = tid + i * 256;
            int k = c >> 4, cn = c & 15;
            CP16(sb + k * 256 + ((cn ^ ((k & 7) << 1)) << 4),
                 Bk + (long long)k * HO + cn * 8);
        }
        asm volatile("cp.async.commit_group;\n");
    };

    loadB(0, 0);
    loadB(1, 1);

    float acc[2][8][4] = {};
    const int g = lane >> 2, t = lane & 3;

    for (int s = 0; s < 32; s++) {
        if (s + 1 < 32) asm volatile("cp.async.wait_group 1;\n");
        else            asm volatile("cp.async.wait_group 0;\n");
        __syncthreads();
        if (s + 2 < 32) loadB((s + 2) % 3, s + 2);

        const unsigned sa = sAb + (unsigned)(s & 3) * 16384u;
        const unsigned sb = sBb + (unsigned)(s % 3) * BSTG;
#pragma unroll
        for (int ks = 0; ks < 4; ks++) {
            const int k16 = ks * 2 + (lane >> 4);
            unsigned af[2][4];
#pragma unroll
            for (int mi = 0; mi < 2; mi++) {
                int m = wm * 32 + mi * 16 + (lane & 15);
                ldsm4(af[mi][0], af[mi][1], af[mi][2], af[mi][3],
                      sa + m * 128 + ((k16 ^ (m & 7)) << 4));
            }
            unsigned bf[8][2];
#pragma unroll
            for (int nj = 0; nj < 4; nj++) {
                int k = ks * 16 + (lane & 15);
                int cn = wn * 8 + nj * 2 + (lane >> 4);
                unsigned t0, t1, t2, t3;
                ldsm4t(t0, t1, t2, t3, sb + k * 256 + ((cn ^ ((k & 7) << 1)) << 4));
                bf[nj * 2][0] = t0; bf[nj * 2][1] = t1;
                bf[nj * 2 + 1][0] = t2; bf[nj * 2 + 1][1] = t3;
            }
#pragma unroll
            for (int mi = 0; mi < 2; mi++)
#pragma unroll
                for (int ni = 0; ni < 8; ni++)
                    mma16816(acc[mi][ni], af[mi], bf[ni]);
        }

        if ((s & 3) == 3) {
            // Epilogue for n-chunk s>>2 (R8 epilogue; overlaps B prefetch)
            const int cb = h * HO + (s >> 2) * 128;
#pragma unroll
            for (int mi = 0; mi < 2; mi++) {
#pragma unroll
                for (int ni = 0; ni < 8; ni++) {
                    int r = r0 + wm * 32 + mi * 16 + g;
                    int c = cb + wn * 64 + ni * 8 + t * 2;
                    float b0 = __ldg(bias + c), b1 = __ldg(bias + c + 1);
                    float v0 = gelu_f(acc[mi][ni][0] + b0);
                    float v1 = gelu_f(acc[mi][ni][1] + b1);
                    *(__half2*)(g_h + (long long)r * MD + c) = __floats2half2_rn(v0, v1);
                    v0 = gelu_f(acc[mi][ni][2] + b0);
                    v1 = gelu_f(acc[mi][ni][3] + b1);
                    *(__half2*)(g_h + (long long)(r + 8) * MD + c) = __floats2half2_rn(v0, v1);
                    acc[mi][ni][0] = acc[mi][ni][1] = acc[mi][ni][2] = acc[mi][ni][3] = 0.f;
                }
            }
        }
    }
}

// ---------------------------------------------------------------------------
// k_down: exact R8/R12 golden kernel (measured 187 us; unchanged).
// ---------------------------------------------------------------------------
__global__ void __launch_bounds__(256, 2) k_down(const float* __restrict__ bias,
                                                 const int* __restrict__ perm,
                                                 float* __restrict__ out) {
    constexpr int KT = 16;
    extern __shared__ char smem[];
    constexpr int ASTG = 128 * 128;
    constexpr int BSTG = 64 * 256;
    const unsigned sAb = (unsigned)__cvta_generic_to_shared(smem);
    const unsigned sBb = sAb + 3 * ASTG;

    const int h  = blockIdx.x >> 1;
    const int nt = blockIdx.x & 1;
    const int r0 = blockIdx.y << 7;
    const int n0 = nt << 7;
    const int tid = threadIdx.x;
    const int lane = tid & 31, warp = tid >> 5;
    const int wm = warp & 3, wn = warp >> 2;

    const __half* Ag = g_h + (long long)r0 * MD + h * HO;
    const __half* Bg = g_w2 + (long long)h * HO * HI + n0;

    auto load_stage = [&](int stage, int kt) {
        const unsigned sa = sAb + stage * ASTG;
        const unsigned sb = sBb + stage * BSTG;
        const __half* Agk = Ag + kt * 64;
        const __half* Bgk = Bg + (long long)kt * 64 * HI;
#pragma unroll
        for (int i = 0; i < 4; i++) {
            int c = tid + i * 256;
            int m = c >> 3, g = c & 7;
            CP16(sa + m * 128 + ((g ^ (m & 7)) << 4), Agk + (long long)m * MD + g * 8);
        }
#pragma unroll
        for (int i = 0; i < 4; i++) {
            int c = tid + i * 256;
            int k = c >> 4, cn = c & 15;
            CP16(sb + k * 256 + ((cn ^ ((k & 7) << 1)) << 4), Bgk + (long long)k * HI + cn * 8);
        }
        asm volatile("cp.async.commit_group;\n");
    };

    float acc[2][8][4] = {};

    load_stage(0, 0);

    for (int kt = 0; kt < KT; kt++) {
        if (kt + 1 < KT) {
            load_stage((kt + 1) % 3, kt + 1);
            asm volatile("cp.async.wait_group 1;\n");
        } else {
            asm volatile("cp.async.wait_group 0;\n");
        }
        __syncthreads();
        const int stg = kt % 3;
        const unsigned sa = sAb + stg * ASTG;
        const unsigned sb = sBb + stg * BSTG;
#pragma unroll
        for (int ks = 0; ks < 4; ks++) {
            const int k16 = ks * 2 + (lane >> 4);
            unsigned af[2][4];
#pragma unroll
            for (int mi = 0; mi < 2; mi++) {
                int m = wm * 32 + mi * 16 + (lane & 15);
                ldsm4(af[mi][0], af[mi][1], af[mi][2], af[mi][3],
                      sa + m * 128 + ((k16 ^ (m & 7)) << 4));
            }
            unsigned bf[8][2];
#pragma unroll
            for (int nj = 0; nj < 4; nj++) {
                int k = ks * 16 + (lane & 15);
                int cn = wn * 8 + nj * 2 + (lane >> 4);
                unsigned t0, t1, t2, t3;
                ldsm4t(t0, t1, t2, t3, sb + k * 256 + ((cn ^ ((k & 7) << 1)) << 4));
                bf[nj * 2][0] = t0; bf[nj * 2][1] = t1;
                bf[nj * 2 + 1][0] = t2; bf[nj * 2 + 1][1] = t3;
            }
#pragma unroll
            for (int mi = 0; mi < 2; mi++)
#pragma unroll
                for (int ni = 0; ni < 8; ni++)
                    mma16816(acc[mi][ni], af[mi], bf[ni]);
        }
    }

    const int g = lane >> 2, t = lane & 3;
    const int cb = h * HI + n0;
#pragma unroll
    for (int mi = 0; mi < 2; mi++) {
#pragma unroll
        for (int ni = 0; ni < 8; ni++) {
            int r = r0 + wm * 32 + mi * 16 + g;
            int c = cb + wn * 64 + ni * 8 + t * 2;
            float b0 = __ldg(bias + c), b1 = __ldg(bias + c + 1);
            int p = __ldg(perm + c);   // c even; 64-chunk perm => perm[c+1]=perm[c]+1
            float2 o0; o0.x = acc[mi][ni][0] + b0; o0.y = acc[mi][ni][1] + b1;
            *(float2*)(out + (long long)r * FD + p) = o0;
            float2 o1; o1.x = acc[mi][ni][2] + b0; o1.y = acc[mi][ni][3] + b1;
            *(float2*)(out + (long long)(r + 8) * FD + p) = o1;
        }
    }
}

extern "C" void kernel_launch(void* const* d_in, const int* in_sizes, int n_in,
                              void* d_out, int out_size) {
    const float* x      = (const float*)d_in[0];
    const int*   perm   = (const int*)d_in[1];
    const float* w_up   = (const float*)d_in[2];
    const float* b_up   = (const float*)d_in[3];
    const float* w_down = (const float*)d_in[4];
    const float* b_down = (const float*)d_in[5];
    float* out = (float*)d_out;

    k_prep_x<<<(NB * FD / 4 + 255) / 256, 256>>>(x, perm);
    k_prep_w<<<(NH * HI * HO / 4 + 255) / 256, 256>>>(w_up, w_down);

    constexpr int SMEM_UP = 65536 + 3 * (64 * 256);    // 64K A + 48K B = 114688
    constexpr int SMEM_DN = 3 * (128 * 128 + 64 * 256);  // 98304
    cudaFuncSetAttribute(k_up_ares, cudaFuncAttributeMaxDynamicSharedMemorySize, SMEM_UP);
    cudaFuncSetAttribute(k_down,   cudaFuncAttributeMaxDynamicSharedMemorySize, SMEM_DN);

    dim3 g1(NH, NB / 128);       // (16, 64): A-resident
    k_up_ares<<<g1, 256, SMEM_UP>>>(b_up);

    dim3 g2(NH * 2, NB / 128);   // (32, 64)
    k_down<<<g2, 256, SMEM_DN>>>(b_down, perm, out);
}

// round 15
// speedup vs baseline: 1.4387x; 1.1292x over previous
#include <cuda_runtime.h>
#include <cuda_fp16.h>
#include <cstdint>

#define NB 8192
#define FD 4096
#define NH 16
#define HI 256
#define HO 1024
#define MD 16384

// Scratch (device globals — no allocation in kernel_launch)
__device__ __half g_xperm[NB * FD];                 // 64 MB
__device__ __half g_w1[NH * HI * HO];               // 8 MB  [h][k=HI][n=HO]
__device__ __half g_w2[NH * HO * HI];               // 8 MB  [h][k=HO][n=HI]
__device__ __half g_h[(long long)NB * MD];          // 256 MB

// Fast gelu: tanh-form with MUFU tanh.approx (5 FMA-class ops + 1 MUFU).
// 0.7978845608 = sqrt(2/pi); 0.0356774081 = 0.044715 * sqrt(2/pi).
__device__ __forceinline__ float gelu_f(float v) {
    float u = v * v;
    float inner = v * fmaf(0.0356774081f, u, 0.7978845608f);
    float th;
    asm("tanh.approx.f32 %0, %1;" : "=f"(th) : "f"(inner));
    float hv = 0.5f * v;
    return fmaf(hv, th, hv);
}

__device__ __forceinline__ void ldsm4(unsigned &r0, unsigned &r1, unsigned &r2, unsigned &r3, unsigned addr) {
    asm volatile("ldmatrix.sync.aligned.m8n8.x4.shared.b16 {%0,%1,%2,%3},[%4];"
                 : "=r"(r0), "=r"(r1), "=r"(r2), "=r"(r3) : "r"(addr));
}
__device__ __forceinline__ void ldsm4t(unsigned &r0, unsigned &r1, unsigned &r2, unsigned &r3, unsigned addr) {
    asm volatile("ldmatrix.sync.aligned.m8n8.x4.trans.shared.b16 {%0,%1,%2,%3},[%4];"
                 : "=r"(r0), "=r"(r1), "=r"(r2), "=r"(r3) : "r"(addr));
}
__device__ __forceinline__ void mma16816(float c[4], const unsigned a[4], const unsigned b[2]) {
    asm volatile("mma.sync.aligned.m16n8k16.row.col.f32.f16.f16.f32 "
                 "{%0,%1,%2,%3},{%4,%5,%6,%7},{%8,%9},{%0,%1,%2,%3};"
                 : "+f"(c[0]), "+f"(c[1]), "+f"(c[2]), "+f"(c[3])
                 : "r"(a[0]), "r"(a[1]), "r"(a[2]), "r"(a[3]), "r"(b[0]), "r"(b[1]));
}
#define CP16(s, g) asm volatile("cp.async.cg.shared.global [%0], [%1], 16;\n" :: "r"(s), "l"(g))

// ---------------------------------------------------------------------------
// Prep kernels (unchanged, validated)
// ---------------------------------------------------------------------------
__global__ void __launch_bounds__(256) k_prep_x(const float* __restrict__ x,
                                                const int* __restrict__ perm) {
    int i = blockIdx.x * 256 + threadIdx.x;
    if (i >= NB * FD / 4) return;
    int b  = i >> 10;
    int k4 = (i & 1023) << 2;
    int p  = __ldg(perm + k4);
    const float4 v = *(const float4*)(x + (long long)b * FD + p);
    __half2* dst = (__half2*)(g_xperm + (long long)b * FD + k4);
    dst[0] = __floats2half2_rn(v.x, v.y);
    dst[1] = __floats2half2_rn(v.z, v.w);
}

__global__ void __launch_bounds__(256) k_prep_w(const float* __restrict__ wu,
                                                const float* __restrict__ wd) {
    int i = blockIdx.x * 256 + threadIdx.x;
    const int N4 = NH * HI * HO / 4;
    if (i >= N4) return;
    float4 a = *(const float4*)(wu + (long long)i * 4);
    __half2* d1 = (__half2*)(g_w1 + (long long)i * 4);
    d1[0] = __floats2half2_rn(a.x, a.y);
    d1[1] = __floats2half2_rn(a.z, a.w);
    float4 b = *(const float4*)(wd + (long long)i * 4);
    __half2* d2 = (__half2*)(g_w2 + (long long)i * 4);
    d2[0] = __floats2half2_rn(b.x, b.y);
    d2[1] = __floats2half2_rn(b.z, b.w);
}

// ---------------------------------------------------------------------------
// k_up_ares: GEMM1 with A-RESIDENT smem (R14 validated). Only gelu changed.
// ---------------------------------------------------------------------------
__global__ void __launch_bounds__(256, 2) k_up_ares(const float* __restrict__ bias) {
    extern __shared__ char smem[];
    constexpr int BSTG = 64 * 256;         // 16 KB per W1 stage
    const unsigned sAb = (unsigned)__cvta_generic_to_shared(smem);   // 64 KB A
    const unsigned sBb = sAb + 65536u;                               // 3 x 16 KB B

    const int h  = blockIdx.x;
    const int r0 = blockIdx.y << 7;
    const int tid = threadIdx.x;
    const int lane = tid & 31, warp = tid >> 5;
    const int wm = warp & 3, wn = warp >> 2;

    const __half* Ag = g_xperm + (long long)r0 * FD + h * HI;
    const __half* W1g = g_w1 + (long long)h * HI * HO;

    // A load (once): 128 rows x 32 granules
#pragma unroll
    for (int i = 0; i < 16; i++) {
        int c = tid + i * 256;
        int m = c >> 5, gk = c & 31;
        CP16(sAb + (gk >> 3) * 16384 + m * 128 + (((gk & 7) ^ (m & 7)) << 4),
             Ag + (long long)m * FD + gk * 8);
    }
    asm volatile("cp.async.commit_group;\n");

    auto loadB = [&](int st, int s) {
        const __half* Bk = W1g + (long long)((s & 3) * 64) * HO + (s >> 2) * 128;
        const unsigned sb = sBb + (unsigned)st * BSTG;
#pragma unroll
        for (int i = 0; i < 4; i++) {
            int c = tid + i * 256;
            int k = c >> 4, cn = c & 15;
            CP16(sb + k * 256 + ((cn ^ ((k & 7) << 1)) << 4),
                 Bk + (long long)k * HO + cn * 8);
        }
        asm volatile("cp.async.commit_group;\n");
    };

    loadB(0, 0);
    loadB(1, 1);

    float acc[2][8][4] = {};
    const int g = lane >> 2, t = lane & 3;

    for (int s = 0; s < 32; s++) {
        if (s + 1 < 32) asm volatile("cp.async.wait_group 1;\n");
        else            asm volatile("cp.async.wait_group 0;\n");
        __syncthreads();
        if (s + 2 < 32) loadB((s + 2) % 3, s + 2);

        const unsigned sa = sAb + (unsigned)(s & 3) * 16384u;
        const unsigned sb = sBb + (unsigned)(s % 3) * BSTG;
#pragma unroll
        for (int ks = 0; ks < 4; ks++) {
            const int k16 = ks * 2 + (lane >> 4);
            unsigned af[2][4];
#pragma unroll
            for (int mi = 0; mi < 2; mi++) {
                int m = wm * 32 + mi * 16 + (lane & 15);
                ldsm4(af[mi][0], af[mi][1], af[mi][2], af[mi][3],
                      sa + m * 128 + ((k16 ^ (m & 7)) << 4));
            }
            unsigned bf[8][2];
#pragma unroll
            for (int nj = 0; nj < 4; nj++) {
                int k = ks * 16 + (lane & 15);
                int cn = wn * 8 + nj * 2 + (lane >> 4);
                unsigned t0, t1, t2, t3;
                ldsm4t(t0, t1, t2, t3, sb + k * 256 + ((cn ^ ((k & 7) << 1)) << 4));
                bf[nj * 2][0] = t0; bf[nj * 2][1] = t1;
                bf[nj * 2 + 1][0] = t2; bf[nj * 2 + 1][1] = t3;
            }
#pragma unroll
            for (int mi = 0; mi < 2; mi++)
#pragma unroll
                for (int ni = 0; ni < 8; ni++)
                    mma16816(acc[mi][ni], af[mi], bf[ni]);
        }

        if ((s & 3) == 3) {
            const int cb = h * HO + (s >> 2) * 128;
#pragma unroll
            for (int mi = 0; mi < 2; mi++) {
#pragma unroll
                for (int ni = 0; ni < 8; ni++) {
                    int r = r0 + wm * 32 + mi * 16 + g;
                    int c = cb + wn * 64 + ni * 8 + t * 2;
                    float b0 = __ldg(bias + c), b1 = __ldg(bias + c + 1);
                    float v0 = gelu_f(acc[mi][ni][0] + b0);
                    float v1 = gelu_f(acc[mi][ni][1] + b1);
                    *(__half2*)(g_h + (long long)r * MD + c) = __floats2half2_rn(v0, v1);
                    v0 = gelu_f(acc[mi][ni][2] + b0);
                    v1 = gelu_f(acc[mi][ni][3] + b1);
                    *(__half2*)(g_h + (long long)(r + 8) * MD + c) = __floats2half2_rn(v0, v1);
                    acc[mi][ni][0] = acc[mi][ni][1] = acc[mi][ni][2] = acc[mi][ni][3] = 0.f;
                }
            }
        }
    }
}

// ---------------------------------------------------------------------------
// k_down: exact golden kernel (measured 187 us; unchanged).
// ---------------------------------------------------------------------------
__global__ void __launch_bounds__(256, 2) k_down(const float* __restrict__ bias,
                                                 const int* __restrict__ perm,
                                                 float* __restrict__ out) {
    constexpr int KT = 16;
    extern __shared__ char smem[];
    constexpr int ASTG = 128 * 128;
    constexpr int BSTG = 64 * 256;
    const unsigned sAb = (unsigned)__cvta_generic_to_shared(smem);
    const unsigned sBb = sAb + 3 * ASTG;

    const int h  = blockIdx.x >> 1;
    const int nt = blockIdx.x & 1;
    const int r0 = blockIdx.y << 7;
    const int n0 = nt << 7;
    const int tid = threadIdx.x;
    const int lane = tid & 31, warp = tid >> 5;
    const int wm = warp & 3, wn = warp >> 2;

    const __half* Ag = g_h + (long long)r0 * MD + h * HO;
    const __half* Bg = g_w2 + (long long)h * HO * HI + n0;

    auto load_stage = [&](int stage, int kt) {
        const unsigned sa = sAb + stage * ASTG;
        const unsigned sb = sBb + stage * BSTG;
        const __half* Agk = Ag + kt * 64;
        const __half* Bgk = Bg + (long long)kt * 64 * HI;
#pragma unroll
        for (int i = 0; i < 4; i++) {
            int c = tid + i * 256;
            int m = c >> 3, g = c & 7;
            CP16(sa + m * 128 + ((g ^ (m & 7)) << 4), Agk + (long long)m * MD + g * 8);
        }
#pragma unroll
        for (int i = 0; i < 4; i++) {
            int c = tid + i * 256;
            int k = c >> 4, cn = c & 15;
            CP16(sb + k * 256 + ((cn ^ ((k & 7) << 1)) << 4), Bgk + (long long)k * HI + cn * 8);
        }
        asm volatile("cp.async.commit_group;\n");
    };

    float acc[2][8][4] = {};

    load_stage(0, 0);

    for (int kt = 0; kt < KT; kt++) {
        if (kt + 1 < KT) {
            load_stage((kt + 1) % 3, kt + 1);
            asm volatile("cp.async.wait_group 1;\n");
        } else {
            asm volatile("cp.async.wait_group 0;\n");
        }
        __syncthreads();
        const int stg = kt % 3;
        const unsigned sa = sAb + stg * ASTG;
        const unsigned sb = sBb + stg * BSTG;
#pragma unroll
        for (int ks = 0; ks < 4; ks++) {
            const int k16 = ks * 2 + (lane >> 4);
            unsigned af[2][4];
#pragma unroll
            for (int mi = 0; mi < 2; mi++) {
                int m = wm * 32 + mi * 16 + (lane & 15);
                ldsm4(af[mi][0], af[mi][1], af[mi][2], af[mi][3],
                      sa + m * 128 + ((k16 ^ (m & 7)) << 4));
            }
            unsigned bf[8][2];
#pragma unroll
            for (int nj = 0; nj < 4; nj++) {
                int k = ks * 16 + (lane & 15);
                int cn = wn * 8 + nj * 2 + (lane >> 4);
                unsigned t0, t1, t2, t3;
                ldsm4t(t0, t1, t2, t3, sb + k * 256 + ((cn ^ ((k & 7) << 1)) << 4));
                bf[nj * 2][0] = t0; bf[nj * 2][1] = t1;
                bf[nj * 2 + 1][0] = t2; bf[nj * 2 + 1][1] = t3;
            }
#pragma unroll
            for (int mi = 0; mi < 2; mi++)
#pragma unroll
                for (int ni = 0; ni < 8; ni++)
                    mma16816(acc[mi][ni], af[mi], bf[ni]);
        }
    }

    const int g = lane >> 2, t = lane & 3;
    const int cb = h * HI + n0;
#pragma unroll
    for (int mi = 0; mi < 2; mi++) {
#pragma unroll
        for (int ni = 0; ni < 8; ni++) {
            int r = r0 + wm * 32 + mi * 16 + g;
            int c = cb + wn * 64 + ni * 8 + t * 2;
            float b0 = __ldg(bias + c), b1 = __ldg(bias + c + 1);
            int p = __ldg(perm + c);   // c even; 64-chunk perm => perm[c+1]=perm[c]+1
            float2 o0; o0.x = acc[mi][ni][0] + b0; o0.y = acc[mi][ni][1] + b1;
            *(float2*)(out + (long long)r * FD + p) = o0;
            float2 o1; o1.x = acc[mi][ni][2] + b0; o1.y = acc[mi][ni][3] + b1;
            *(float2*)(out + (long long)(r + 8) * FD + p) = o1;
        }
    }
}

extern "C" void kernel_launch(void* const* d_in, const int* in_sizes, int n_in,
                              void* d_out, int out_size) {
    const float* x      = (const float*)d_in[0];
    const int*   perm   = (const int*)d_in[1];
    const float* w_up   = (const float*)d_in[2];
    const float* b_up   = (const float*)d_in[3];
    const float* w_down = (const float*)d_in[4];
    const float* b_down = (const float*)d_in[5];
    float* out = (float*)d_out;

    k_prep_x<<<(NB * FD / 4 + 255) / 256, 256>>>(x, perm);
    k_prep_w<<<(NH * HI * HO / 4 + 255) / 256, 256>>>(w_up, w_down);

    constexpr int SMEM_UP = 65536 + 3 * (64 * 256);      // 114688
    constexpr int SMEM_DN = 3 * (128 * 128 + 64 * 256);  // 98304
    cudaFuncSetAttribute(k_up_ares, cudaFuncAttributeMaxDynamicSharedMemorySize, SMEM_UP);
    cudaFuncSetAttribute(k_down,   cudaFuncAttributeMaxDynamicSharedMemorySize, SMEM_DN);

    dim3 g1(NH, NB / 128);       // (16, 64): A-resident
    k_up_ares<<<g1, 256, SMEM_UP>>>(b_up);

    dim3 g2(NH * 2, NB / 128);   // (32, 64)
    k_down<<<g2, 256, SMEM_DN>>>(b_down, perm, out);
}